// round 11
// baseline (speedup 1.0000x reference)
#include <cuda_runtime.h>
#include <cuda_bf16.h>
#include <math.h>

#define NWIN    2048
#define NTOKENS 200704
#define XELEMS  (NTOKENS * 96)
#define SCALEL  0.25503472f      // (1/sqrt(32)) * log2(e)

// ---------------- device scratch ----------------
__device__ float g_xmid[XELEMS];
__device__ __nv_bfloat16 g_bias_bf[3 * 98 * 112];  // [h][i][j], *log2e, pad j>=98 = -30000
__device__ __nv_bfloat16 g_wqkv[288 * 96];
__device__ __nv_bfloat16 g_wproj[96 * 96];
__device__ __nv_bfloat16 g_fc1[384 * 96];
__device__ __nv_bfloat16 g_fc2[96 * 384];

// ---------------- prep ----------------
__global__ void prep_kernel(const float* __restrict__ qkv_w,
                            const float* __restrict__ proj_w,
                            const float* __restrict__ fc1_w,
                            const float* __restrict__ fc2_w,
                            const float* __restrict__ rpb)
{
    int tid = blockIdx.x * blockDim.x + threadIdx.x;
    int stride = gridDim.x * blockDim.x;
    for (int i = tid; i < 288 * 96; i += stride) g_wqkv[i]  = __float2bfloat16_rn(qkv_w[i]);
    for (int i = tid; i < 96 * 96;  i += stride) g_wproj[i] = __float2bfloat16_rn(proj_w[i]);
    for (int i = tid; i < 384 * 96; i += stride) g_fc1[i]   = __float2bfloat16_rn(fc1_w[i]);
    for (int i = tid; i < 96 * 384; i += stride) g_fc2[i]   = __float2bfloat16_rn(fc2_w[i]);
    for (int idx = tid; idx < 3 * 98 * 112; idx += stride) {
        int h = idx / (98 * 112);
        int r = idx - h * 98 * 112;
        int n = r / 112, m = r - n * 112;
        float v;
        if (m < 98) {
            int nd = n / 49, nh = (n % 49) / 7, nw = n % 7;
            int md = m / 49, mh = (m % 49) / 7, mw = m % 7;
            int rel = (nd - md + 1) * 169 + (nh - mh + 6) * 13 + (nw - mw + 6);
            v = rpb[rel * 3 + h] * 1.4426950408889634f;
        } else {
            v = -30000.f;
        }
        g_bias_bf[idx] = __float2bfloat16_rn(v);
    }
}

// ---------------- helpers ----------------
__device__ __forceinline__ unsigned sm_u32(const void* p)
{
    return (unsigned)__cvta_generic_to_shared(p);
}

__device__ __forceinline__ void cpa16(void* dst, const void* src)
{
    asm volatile("cp.async.cg.shared.global [%0], [%1], 16;\n"
                 :: "r"(sm_u32(dst)), "l"(src));
}

#define CPA_COMMIT() asm volatile("cp.async.commit_group;\n" ::: "memory")
#define CPA_WAIT0()  asm volatile("cp.async.wait_group 0;\n" ::: "memory")

__device__ __forceinline__ float ex2f(float x)
{
    float r;
    asm("ex2.approx.f32 %0, %1;\n" : "=f"(r) : "f"(x));
    return r;
}

__device__ __forceinline__ float tanhf_hw(float x)
{
    float r;
    asm("tanh.approx.f32 %0, %1;\n" : "=f"(r) : "f"(x));
    return r;
}

__device__ __forceinline__ void ldsm4(unsigned addr, unsigned& r0, unsigned& r1,
                                      unsigned& r2, unsigned& r3)
{
    asm volatile("ldmatrix.sync.aligned.m8n8.x4.shared.b16 {%0,%1,%2,%3}, [%4];\n"
                 : "=r"(r0), "=r"(r1), "=r"(r2), "=r"(r3) : "r"(addr));
}

__device__ __forceinline__ void ldsm4t(unsigned addr, unsigned& r0, unsigned& r1,
                                       unsigned& r2, unsigned& r3)
{
    asm volatile("ldmatrix.sync.aligned.m8n8.x4.trans.shared.b16 {%0,%1,%2,%3}, [%4];\n"
                 : "=r"(r0), "=r"(r1), "=r"(r2), "=r"(r3) : "r"(addr));
}

__device__ __forceinline__ void mmabf(float* c, unsigned a0, unsigned a1, unsigned a2,
                                      unsigned a3, unsigned b0, unsigned b1)
{
    asm volatile(
        "mma.sync.aligned.m16n8k16.row.col.f32.bf16.bf16.f32 "
        "{%0,%1,%2,%3}, {%4,%5,%6,%7}, {%8,%9}, {%0,%1,%2,%3};\n"
        : "+f"(c[0]), "+f"(c[1]), "+f"(c[2]), "+f"(c[3])
        : "r"(a0), "r"(a1), "r"(a2), "r"(a3), "r"(b0), "r"(b1));
}

// plain 16x32 macro-tile
template <int KSTEPS, int LDA, int LDB>
__device__ __forceinline__ void gemm16x32(const __nv_bfloat16* __restrict__ A,
                                          const __nv_bfloat16* __restrict__ B,
                                          int m0, int n0, int lane, float c[4][4])
{
    const int l7 = lane & 7, s8 = (lane >> 3) & 1, s16 = (lane >> 4) & 1;
    unsigned aA  = sm_u32(A + (m0 + s8 * 8 + l7) * LDA + s16 * 8);
    unsigned aB0 = sm_u32(B + (n0 + s16 * 8 + l7) * LDB + s8 * 8);
    unsigned aB1 = aB0 + 16 * LDB * 2;
#pragma unroll
    for (int ks = 0; ks < KSTEPS; ++ks) {
        unsigned a0, a1, a2, a3, b0, b1, b2, b3;
        ldsm4(aA + ks * 32, a0, a1, a2, a3);
        ldsm4(aB0 + ks * 32, b0, b1, b2, b3);
        mmabf(c[0], a0, a1, a2, a3, b0, b1);
        mmabf(c[1], a0, a1, a2, a3, b2, b3);
        ldsm4(aB1 + ks * 32, b0, b1, b2, b3);
        mmabf(c[2], a0, a1, a2, a3, b0, b1);
        mmabf(c[3], a0, a1, a2, a3, b2, b3);
    }
}

// 32x32 macro-tile (MLP): 4 ldsm per 8 mma
template <int KSTEPS, int LDA, int LDB>
__device__ __forceinline__ void gemm32x32(const __nv_bfloat16* __restrict__ A,
                                          const __nv_bfloat16* __restrict__ B,
                                          int m0, int n0, int lane, float c[2][4][4])
{
    const int l7 = lane & 7, s8 = (lane >> 3) & 1, s16 = (lane >> 4) & 1;
    unsigned aA0 = sm_u32(A + (m0 + s8 * 8 + l7) * LDA + s16 * 8);
    unsigned aA1 = aA0 + 16 * LDA * 2;
    unsigned aB0 = sm_u32(B + (n0 + s16 * 8 + l7) * LDB + s8 * 8);
    unsigned aB1 = aB0 + 16 * LDB * 2;
#pragma unroll
    for (int ks = 0; ks < KSTEPS; ++ks) {
        unsigned a00, a01, a02, a03, a10, a11, a12, a13, b0, b1, b2, b3;
        ldsm4(aA0 + ks * 32, a00, a01, a02, a03);
        ldsm4(aA1 + ks * 32, a10, a11, a12, a13);
        ldsm4(aB0 + ks * 32, b0, b1, b2, b3);
        mmabf(c[0][0], a00, a01, a02, a03, b0, b1);
        mmabf(c[0][1], a00, a01, a02, a03, b2, b3);
        mmabf(c[1][0], a10, a11, a12, a13, b0, b1);
        mmabf(c[1][1], a10, a11, a12, a13, b2, b3);
        ldsm4(aB1 + ks * 32, b0, b1, b2, b3);
        mmabf(c[0][2], a00, a01, a02, a03, b0, b1);
        mmabf(c[0][3], a00, a01, a02, a03, b2, b3);
        mmabf(c[1][2], a10, a11, a12, a13, b0, b1);
        mmabf(c[1][3], a10, a11, a12, a13, b2, b3);
    }
}

__device__ __forceinline__ void st_bf2(__nv_bfloat16* p, float x, float y)
{
    __nv_bfloat162 v = __floats2bfloat162_rn(x, y);
    *reinterpret_cast<__nv_bfloat162*>(p) = v;
}

__device__ __forceinline__ unsigned pack_bf2(float x, float y)
{
    __nv_bfloat162 v = __floats2bfloat162_rn(x, y);
    return *reinterpret_cast<unsigned*>(&v);
}

// stage a 96x96 bf16 weight block into smem stride 104
__device__ __forceinline__ void stage_w(__nv_bfloat16* dst, const __nv_bfloat16* src,
                                        int tid, int nthr)
{
    for (int idx = tid; idx < 96 * 12; idx += nthr) {
        int r = idx / 12, q = idx % 12;
        cpa16(dst + r * 104 + q * 8, src + r * 96 + q * 8);
    }
}

// ---------------- kernel 1 smem layout (bytes) ----------------
#define A_XN 0          // XN; Wproj for the proj phase
#define A_K  23296      // Wv staging, then K
#define A_V  46592      // V
#define A_AO 69888      // Wk staging, then AO
#define A_W  93184      // Wq (resident through flash)
#define SM1_BYTES 113152

// K/V gemm tiles (12-warp distribution): C[112x96] with zeroed pad rows
__device__ __forceinline__ void qkv_tiles(const __nv_bfloat16* XN, const __nv_bfloat16* W,
                                          __nv_bfloat16* DST, const float* qkv_b,
                                          int bias_off, int wid, int lane, int g, int t4)
{
    for (int mac = wid; mac < 21; mac += 12) {
        int mt = mac / 3, nt = mac % 3;
        int m0 = mt * 16, n0 = nt * 32;
        float c[4][4] = {};
        gemm16x32<6, 104, 104>(XN, W, m0, n0, lane, c);
#pragma unroll
        for (int nn = 0; nn < 4; ++nn) {
            int d = n0 + nn * 8 + 2 * t4;
            float b0 = __ldg(&qkv_b[bias_off + d]);
            float b1 = __ldg(&qkv_b[bias_off + d + 1]);
#pragma unroll
            for (int rh = 0; rh < 2; ++rh) {
                int trow = m0 + g + rh * 8;
                float v0 = c[nn][rh * 2]     + b0;
                float v1 = c[nn][rh * 2 + 1] + b1;
                if (trow >= 98) { v0 = 0.f; v1 = 0.f; }   // K/V pads are reduction dims
                st_bf2(DST + trow * 104 + d, v0, v1);
            }
        }
    }
}

__global__ __launch_bounds__(384, 2)
void attn_kernel(const float* __restrict__ x,
                 const float* __restrict__ n1w, const float* __restrict__ n1b,
                 const float* __restrict__ qkv_b, const float* __restrict__ proj_b)
{
    extern __shared__ char smc[];
    __nv_bfloat16* XN = (__nv_bfloat16*)(smc + A_XN);
    __nv_bfloat16* Kb = (__nv_bfloat16*)(smc + A_K);
    __nv_bfloat16* V  = (__nv_bfloat16*)(smc + A_V);
    __nv_bfloat16* AO = (__nv_bfloat16*)(smc + A_AO);
    __nv_bfloat16* W  = (__nv_bfloat16*)(smc + A_W);
    __shared__ int s_toff[98];

    const int tid = threadIdx.x;
    const int wid = tid >> 5, lane = tid & 31;
    const int g = lane >> 2, t4 = lane & 3;

    // prefetch Wv (into K-buf) and Wq (into W) behind LN
    stage_w(Kb, g_wqkv + 18432, tid, 384);
    stage_w(W, g_wqkv, tid, 384);
    CPA_COMMIT();

    const int widx = blockIdx.x;
    const int b = widx >> 8;
    const int rr = widx & 255;
    const int dblk = rr >> 6, hblk = (rr >> 3) & 7, wblk = rr & 7;
    if (tid < 98) {
        int wd = (tid >= 49);
        int rem = tid - wd * 49;
        int wh = rem / 7, ww = rem - wh * 7;
        s_toff[tid] = (((b * 8 + dblk * 2 + wd) * 56 + hblk * 7 + wh) * 56 + wblk * 7 + ww) * 96;
    }
    // zero XN pad rows
    for (int i = tid; i < 14 * 52; i += 384)
        reinterpret_cast<unsigned*>(XN + 98 * 104)[i] = 0u;
    __syncthreads();   // S1

    // ---- LN1 -> XN bf16 [t][c] ----
    for (int t = wid; t < 98; t += 12) {
        int off = s_toff[t];
        float v0 = x[off + lane];
        float v1 = x[off + lane + 32];
        float v2 = x[off + lane + 64];
        float s = v0 + v1 + v2;
#pragma unroll
        for (int o = 16; o; o >>= 1) s += __shfl_xor_sync(0xffffffffu, s, o);
        float mean = s * (1.f / 96.f);
        float d0 = v0 - mean, d1 = v1 - mean, d2 = v2 - mean;
        float q2 = d0 * d0 + d1 * d1 + d2 * d2;
#pragma unroll
        for (int o = 16; o; o >>= 1) q2 += __shfl_xor_sync(0xffffffffu, q2, o);
        float rstd = rsqrtf(q2 * (1.f / 96.f) + 1e-5f);
        XN[t * 104 + lane] =
            __float2bfloat16_rn(d0 * rstd * __ldg(&n1w[lane]) + __ldg(&n1b[lane]));
        XN[t * 104 + lane + 32] =
            __float2bfloat16_rn(d1 * rstd * __ldg(&n1w[lane + 32]) + __ldg(&n1b[lane + 32]));
        XN[t * 104 + lane + 64] =
            __float2bfloat16_rn(d2 * rstd * __ldg(&n1w[lane + 64]) + __ldg(&n1b[lane + 64]));
    }
    CPA_WAIT0();
    __syncthreads();   // S2: XN + Wv + Wq ready

    stage_w(AO, g_wqkv + 9216, tid, 384);    // Wk (hidden behind V gemm)
    CPA_COMMIT();
    qkv_tiles(XN, Kb, V, qkv_b, 192, wid, lane, g, t4);   // V = XN * Wv
    CPA_WAIT0();
    __syncthreads();   // S3: V + Wk ready; K-buf (Wv) dead

    qkv_tiles(XN, AO, Kb, qkv_b, 96, wid, lane, g, t4);   // K = XN * Wk
    __syncthreads();   // S4: K ready; AO (Wk) dead

    // ---- flash attention: Q in registers, no-max softmax, deferred norm ----
    const int l7 = lane & 7;
    for (int unit = wid; unit < 21; unit += 12) {
        int h = unit / 7, m0 = (unit % 7) * 16;
        const __nv_bfloat16* Kh = Kb + h * 32;

        // Q tile in C-fragments
        unsigned qa[2][4];
        {
            float cq[4][4] = {};
            gemm16x32<6, 104, 104>(XN, W, m0, h * 32, lane, cq);
            float qb0[4], qb1[4];
#pragma unroll
            for (int nn = 0; nn < 4; ++nn) {
                int d = h * 32 + nn * 8 + 2 * t4;
                qb0[nn] = __ldg(&qkv_b[d]);
                qb1[nn] = __ldg(&qkv_b[d + 1]);
            }
#pragma unroll
            for (int ks = 0; ks < 2; ++ks) {
                qa[ks][0] = pack_bf2((cq[2*ks][0] + qb0[2*ks]) * SCALEL,
                                     (cq[2*ks][1] + qb1[2*ks]) * SCALEL);
                qa[ks][1] = pack_bf2((cq[2*ks][2] + qb0[2*ks]) * SCALEL,
                                     (cq[2*ks][3] + qb1[2*ks]) * SCALEL);
                qa[ks][2] = pack_bf2((cq[2*ks+1][0] + qb0[2*ks+1]) * SCALEL,
                                     (cq[2*ks+1][1] + qb1[2*ks+1]) * SCALEL);
                qa[ks][3] = pack_bf2((cq[2*ks+1][2] + qb0[2*ks+1]) * SCALEL,
                                     (cq[2*ks+1][3] + qb1[2*ks+1]) * SCALEL);
            }
        }

        // S tiles -> exp2 immediately -> packed unnormalized probabilities
        int i0 = m0 + g;     if (i0 > 97) i0 = 97;
        int i1 = m0 + g + 8; if (i1 > 97) i1 = 97;
        const __nv_bfloat16* bi0 = g_bias_bf + h * 10976 + i0 * 112;
        const __nv_bfloat16* bi1 = g_bias_bf + h * 10976 + i1 * 112;
        unsigned pa[7][4];
        float sum0 = 0.f, sum1 = 0.f;
#pragma unroll
        for (int j = 0; j < 7; ++j) {
            float st[2][4];
#pragma unroll
            for (int hf = 0; hf < 2; ++hf)
#pragma unroll
                for (int e = 0; e < 4; ++e) st[hf][e] = 0.f;
            unsigned aB = sm_u32(Kh + (j * 16 + ((lane >> 4) & 1) * 8 + l7) * 104 +
                                 ((lane >> 3) & 1) * 8);
#pragma unroll
            for (int ks = 0; ks < 2; ++ks) {
                unsigned b0, b1, b2, b3;
                ldsm4(aB + ks * 32, b0, b1, b2, b3);
                mmabf(st[0], qa[ks][0], qa[ks][1], qa[ks][2], qa[ks][3], b0, b1);
                mmabf(st[1], qa[ks][0], qa[ks][1], qa[ks][2], qa[ks][3], b2, b3);
            }
#pragma unroll
            for (int hf = 0; hf < 2; ++hf) {
                int col = 16 * j + 8 * hf + 2 * t4;
                __nv_bfloat162 b0 = *reinterpret_cast<const __nv_bfloat162*>(bi0 + col);
                __nv_bfloat162 b1 = *reinterpret_cast<const __nv_bfloat162*>(bi1 + col);
                float e0 = ex2f(st[hf][0] + __bfloat162float(b0.x));
                float e1 = ex2f(st[hf][1] + __bfloat162float(b0.y));
                float e2 = ex2f(st[hf][2] + __bfloat162float(b1.x));
                float e3 = ex2f(st[hf][3] + __bfloat162float(b1.y));
                sum0 += e0 + e1;
                sum1 += e2 + e3;
                pa[j][2 * hf]     = pack_bf2(e0, e1);
                pa[j][2 * hf + 1] = pack_bf2(e2, e3);
            }
        }
        sum0 += __shfl_xor_sync(0xffffffffu, sum0, 1);
        sum0 += __shfl_xor_sync(0xffffffffu, sum0, 2);
        sum1 += __shfl_xor_sync(0xffffffffu, sum1, 1);
        sum1 += __shfl_xor_sync(0xffffffffu, sum1, 2);
        float r0 = __fdividef(1.f, sum0), r1 = __fdividef(1.f, sum1);

        // PV on unnormalized probabilities
        float o[2][2][4] = {};
#pragma unroll
        for (int j = 0; j < 7; ++j) {
            unsigned vb = sm_u32(V + (j * 16 + ((lane >> 3) & 1) * 8 + l7) * 104 +
                                 h * 32 + ((lane >> 4) & 1) * 8);
            unsigned b0, b1, b2, b3;
            ldsm4t(vb, b0, b1, b2, b3);
            mmabf(o[0][0], pa[j][0], pa[j][1], pa[j][2], pa[j][3], b0, b1);
            mmabf(o[0][1], pa[j][0], pa[j][1], pa[j][2], pa[j][3], b2, b3);
            ldsm4t(vb + 32, b0, b1, b2, b3);
            mmabf(o[1][0], pa[j][0], pa[j][1], pa[j][2], pa[j][3], b0, b1);
            mmabf(o[1][1], pa[j][0], pa[j][1], pa[j][2], pa[j][3], b2, b3);
        }

        // normalize rows and store AO strip
#pragma unroll
        for (int nc = 0; nc < 2; ++nc)
#pragma unroll
            for (int hf = 0; hf < 2; ++hf) {
                int col = h * 32 + nc * 16 + hf * 8 + 2 * t4;
                st_bf2(AO + (m0 + g) * 104 + col,
                       o[nc][hf][0] * r0, o[nc][hf][1] * r0);
                st_bf2(AO + (m0 + g + 8) * 104 + col,
                       o[nc][hf][2] * r1, o[nc][hf][3] * r1);
            }
    }
    __syncthreads();   // S5: flash done; XN dead

    // stage Wproj into XN region
    stage_w(XN, g_wproj, tid, 384);
    CPA_COMMIT();
    CPA_WAIT0();
    __syncthreads();   // S6: Wproj ready

    // ---- proj + bias + residual ----
    for (int mac = wid; mac < 21; mac += 12) {
        int mt = mac / 3, nt = mac % 3;
        int m0 = mt * 16, n0 = nt * 32;
        float c[4][4] = {};
        gemm16x32<6, 104, 104>(AO, XN, m0, n0, lane, c);
#pragma unroll
        for (int nn = 0; nn < 4; ++nn) {
            int col = n0 + nn * 8 + 2 * t4;
            float pb0 = __ldg(&proj_b[col]), pb1 = __ldg(&proj_b[col + 1]);
#pragma unroll
            for (int rh = 0; rh < 2; ++rh) {
                int trow = m0 + g + rh * 8;
                if (trow < 98) {
                    int off = s_toff[trow] + col;
                    float2 xr = *reinterpret_cast<const float2*>(&x[off]);
                    float2 o2;
                    o2.x = c[nn][rh * 2]     + pb0 + xr.x;
                    o2.y = c[nn][rh * 2 + 1] + pb1 + xr.y;
                    *reinterpret_cast<float2*>(&g_xmid[off]) = o2;
                }
            }
        }
    }
}

// ---------------- kernel 2 ----------------
#define M_X   0            // bf16 [128][104] = 26624
#define M_H   26624        // bf16 [128][104]
#define M_W1  53248        // bf16 [96][104]  = 19968
#define M_W2A 73216
#define M_W2B 93184
#define SM2_BYTES 113152

__device__ __forceinline__ float gelu_fast(float x)
{
    float u = x * x;
    float w = fmaf(0.03567740814f, u, 0.7978845608f);
    float t = tanhf_hw(x * w);
    return fmaf(x * 0.5f, t, x * 0.5f);
}

__global__ __launch_bounds__(384, 2)
void mlp_kernel(const float* __restrict__ n2w, const float* __restrict__ n2b,
                const float* __restrict__ fc1_b, const float* __restrict__ fc2_b,
                float* __restrict__ out)
{
    extern __shared__ char smc[];
    __nv_bfloat16* X  = (__nv_bfloat16*)(smc + M_X);
    __nv_bfloat16* H  = (__nv_bfloat16*)(smc + M_H);
    __nv_bfloat16* W1 = (__nv_bfloat16*)(smc + M_W1);
    __nv_bfloat16* W2buf[2] = { (__nv_bfloat16*)(smc + M_W2A), (__nv_bfloat16*)(smc + M_W2B) };

    const int tid = threadIdx.x;
    const int wid = tid >> 5, lane = tid & 31;
    const int g = lane >> 2, t4 = lane & 3;
    const int tbase = blockIdx.x * 128;

    const int mt = wid / 3, nt = wid % 3;
    const int m0 = mt * 32, n0 = nt * 32;

    // preload chunk-0 weights (hidden behind LN)
    stage_w(W1, g_fc1, tid, 384);
    for (int idx = tid; idx < 96 * 12; idx += 384) {
        int r = idx / 12, q = idx % 12;
        cpa16(W2buf[0] + r * 104 + q * 8, g_fc2 + r * 384 + q * 8);
    }
    CPA_COMMIT();

    // ---- LN2 -> X bf16 ----
    for (int t = wid; t < 128; t += 12) {
        const float* p = g_xmid + (tbase + t) * 96;
        float v0 = p[lane], v1 = p[lane + 32], v2 = p[lane + 64];
        float s = v0 + v1 + v2;
#pragma unroll
        for (int o = 16; o; o >>= 1) s += __shfl_xor_sync(0xffffffffu, s, o);
        float mean = s * (1.f / 96.f);
        float d0 = v0 - mean, d1 = v1 - mean, d2 = v2 - mean;
        float q2 = d0 * d0 + d1 * d1 + d2 * d2;
#pragma unroll
        for (int o = 16; o; o >>= 1) q2 += __shfl_xor_sync(0xffffffffu, q2, o);
        float rstd = rsqrtf(q2 * (1.f / 96.f) + 1e-5f);
        X[t * 104 + lane] =
            __float2bfloat16_rn(d0 * rstd * __ldg(&n2w[lane]) + __ldg(&n2b[lane]));
        X[t * 104 + lane + 32] =
            __float2bfloat16_rn(d1 * rstd * __ldg(&n2w[lane + 32]) + __ldg(&n2b[lane + 32]));
        X[t * 104 + lane + 64] =
            __float2bfloat16_rn(d2 * rstd * __ldg(&n2w[lane + 64]) + __ldg(&n2b[lane + 64]));
    }

    float c2[2][4][4] = {};   // persistent fc2 accumulators

    for (int ch = 0; ch < 4; ++ch) {
        CPA_WAIT0();
        __syncthreads();

        if (ch < 3) {
            for (int idx = tid; idx < 96 * 12; idx += 384) {
                int r = idx / 12, q = idx % 12;
                cpa16(W2buf[(ch + 1) & 1] + r * 104 + q * 8,
                      g_fc2 + r * 384 + (ch + 1) * 96 + q * 8);
            }
            CPA_COMMIT();
        }

        // fc1 tile + GELU -> H
        {
            float c[2][4][4] = {};
            gemm32x32<6, 104, 104>(X, W1, m0, n0, lane, c);
#pragma unroll
            for (int mf = 0; mf < 2; ++mf)
#pragma unroll
                for (int nn = 0; nn < 4; ++nn) {
                    int col = n0 + nn * 8 + 2 * t4;
                    float b0 = __ldg(&fc1_b[ch * 96 + col]);
                    float b1 = __ldg(&fc1_b[ch * 96 + col + 1]);
#pragma unroll
                    for (int rh = 0; rh < 2; ++rh)
                        st_bf2(H + (m0 + mf * 16 + g + rh * 8) * 104 + col,
                               gelu_fast(c[mf][nn][rh * 2] + b0),
                               gelu_fast(c[mf][nn][rh * 2 + 1] + b1));
                }
        }
        __syncthreads();

        if (ch < 3) {
            stage_w(W1, g_fc1 + (ch + 1) * 96 * 96, tid, 384);
            CPA_COMMIT();
        }

        gemm32x32<6, 104, 104>(H, W2buf[ch & 1], m0, n0, lane, c2);
    }

    // ---- epilogue: bias + residual -> out ----
#pragma unroll
    for (int mf = 0; mf < 2; ++mf)
#pragma unroll
        for (int nn = 0; nn < 4; ++nn) {
            int col = n0 + nn * 8 + 2 * t4;
            float b0 = __ldg(&fc2_b[col]), b1 = __ldg(&fc2_b[col + 1]);
#pragma unroll
            for (int rh = 0; rh < 2; ++rh) {
                int off = (tbase + m0 + mf * 16 + g + rh * 8) * 96 + col;
                float2 xr = *reinterpret_cast<const float2*>(&g_xmid[off]);
                float2 o2;
                o2.x = c2[mf][nn][rh * 2]     + b0 + xr.x;
                o2.y = c2[mf][nn][rh * 2 + 1] + b1 + xr.y;
                *reinterpret_cast<float2*>(&out[off]) = o2;
            }
        }
}

// ---------------- launch ----------------
extern "C" void kernel_launch(void* const* d_in, const int* in_sizes, int n_in,
                              void* d_out, int out_size)
{
    const float* x      = (const float*)d_in[0];
    const float* n1w    = (const float*)d_in[1];
    const float* n1b    = (const float*)d_in[2];
    const float* qkv_w  = (const float*)d_in[3];
    const float* qkv_b  = (const float*)d_in[4];
    const float* proj_w = (const float*)d_in[5];
    const float* proj_b = (const float*)d_in[6];
    const float* rpb    = (const float*)d_in[7];
    const float* n2w    = (const float*)d_in[8];
    const float* n2b    = (const float*)d_in[9];
    const float* fc1_w  = (const float*)d_in[10];
    const float* fc1_b  = (const float*)d_in[11];
    const float* fc2_w  = (const float*)d_in[12];
    const float* fc2_b  = (const float*)d_in[13];
    float* out = (float*)d_out;

    cudaFuncSetAttribute(attn_kernel, cudaFuncAttributeMaxDynamicSharedMemorySize, SM1_BYTES);
    cudaFuncSetAttribute(mlp_kernel,  cudaFuncAttributeMaxDynamicSharedMemorySize, SM2_BYTES);

    prep_kernel<<<128, 256>>>(qkv_w, proj_w, fc1_w, fc2_w, rpb);
    attn_kernel<<<NWIN, 384, SM1_BYTES>>>(x, n1w, n1b, qkv_b, proj_b);
    mlp_kernel<<<NTOKENS / 128, 384, SM2_BYTES>>>(n2w, n2b, fc1_b, fc2_b, out);
}

// round 12
// speedup vs baseline: 1.0436x; 1.0436x over previous
#include <cuda_runtime.h>
#include <cuda_bf16.h>
#include <math.h>

#define NWIN    2048
#define NTOKENS 200704
#define XELEMS  (NTOKENS * 96)
#define SCALEL  0.25503472f      // (1/sqrt(32)) * log2(e)

// ---------------- device scratch ----------------
__device__ float g_xmid[XELEMS];
__device__ __nv_bfloat16 g_bias_bf[3 * 98 * 112];  // [h][i][j], *log2e, pad j>=98 = -30000
__device__ __nv_bfloat16 g_wqkv[288 * 96];
__device__ __nv_bfloat16 g_wproj[96 * 96];
__device__ __nv_bfloat16 g_fc1[384 * 96];
__device__ __nv_bfloat16 g_fc2[96 * 384];

// ---------------- prep ----------------
__global__ void prep_kernel(const float* __restrict__ qkv_w,
                            const float* __restrict__ proj_w,
                            const float* __restrict__ fc1_w,
                            const float* __restrict__ fc2_w,
                            const float* __restrict__ rpb)
{
    int tid = blockIdx.x * blockDim.x + threadIdx.x;
    int stride = gridDim.x * blockDim.x;
    for (int i = tid; i < 288 * 96; i += stride) g_wqkv[i]  = __float2bfloat16_rn(qkv_w[i]);
    for (int i = tid; i < 96 * 96;  i += stride) g_wproj[i] = __float2bfloat16_rn(proj_w[i]);
    for (int i = tid; i < 384 * 96; i += stride) g_fc1[i]   = __float2bfloat16_rn(fc1_w[i]);
    for (int i = tid; i < 96 * 384; i += stride) g_fc2[i]   = __float2bfloat16_rn(fc2_w[i]);
    for (int idx = tid; idx < 3 * 98 * 112; idx += stride) {
        int h = idx / (98 * 112);
        int r = idx - h * 98 * 112;
        int n = r / 112, m = r - n * 112;
        float v;
        if (m < 98) {
            int nd = n / 49, nh = (n % 49) / 7, nw = n % 7;
            int md = m / 49, mh = (m % 49) / 7, mw = m % 7;
            int rel = (nd - md + 1) * 169 + (nh - mh + 6) * 13 + (nw - mw + 6);
            v = rpb[rel * 3 + h] * 1.4426950408889634f;
        } else {
            v = -30000.f;
        }
        g_bias_bf[idx] = __float2bfloat16_rn(v);
    }
}

// ---------------- helpers ----------------
__device__ __forceinline__ unsigned sm_u32(const void* p)
{
    return (unsigned)__cvta_generic_to_shared(p);
}

__device__ __forceinline__ void cpa16(void* dst, const void* src)
{
    asm volatile("cp.async.cg.shared.global [%0], [%1], 16;\n"
                 :: "r"(sm_u32(dst)), "l"(src));
}

#define CPA_COMMIT() asm volatile("cp.async.commit_group;\n" ::: "memory")
#define CPA_WAIT0()  asm volatile("cp.async.wait_group 0;\n" ::: "memory")

__device__ __forceinline__ float ex2f(float x)
{
    float r;
    asm("ex2.approx.f32 %0, %1;\n" : "=f"(r) : "f"(x));
    return r;
}

__device__ __forceinline__ float tanhf_hw(float x)
{
    float r;
    asm("tanh.approx.f32 %0, %1;\n" : "=f"(r) : "f"(x));
    return r;
}

__device__ __forceinline__ void ldsm4(unsigned addr, unsigned& r0, unsigned& r1,
                                      unsigned& r2, unsigned& r3)
{
    asm volatile("ldmatrix.sync.aligned.m8n8.x4.shared.b16 {%0,%1,%2,%3}, [%4];\n"
                 : "=r"(r0), "=r"(r1), "=r"(r2), "=r"(r3) : "r"(addr));
}

__device__ __forceinline__ void ldsm4t(unsigned addr, unsigned& r0, unsigned& r1,
                                       unsigned& r2, unsigned& r3)
{
    asm volatile("ldmatrix.sync.aligned.m8n8.x4.trans.shared.b16 {%0,%1,%2,%3}, [%4];\n"
                 : "=r"(r0), "=r"(r1), "=r"(r2), "=r"(r3) : "r"(addr));
}

__device__ __forceinline__ void mmabf(float* c, unsigned a0, unsigned a1, unsigned a2,
                                      unsigned a3, unsigned b0, unsigned b1)
{
    asm volatile(
        "mma.sync.aligned.m16n8k16.row.col.f32.bf16.bf16.f32 "
        "{%0,%1,%2,%3}, {%4,%5,%6,%7}, {%8,%9}, {%0,%1,%2,%3};\n"
        : "+f"(c[0]), "+f"(c[1]), "+f"(c[2]), "+f"(c[3])
        : "r"(a0), "r"(a1), "r"(a2), "r"(a3), "r"(b0), "r"(b1));
}

// plain 16x32 macro-tile
template <int KSTEPS, int LDA, int LDB>
__device__ __forceinline__ void gemm16x32(const __nv_bfloat16* __restrict__ A,
                                          const __nv_bfloat16* __restrict__ B,
                                          int m0, int n0, int lane, float c[4][4])
{
    const int l7 = lane & 7, s8 = (lane >> 3) & 1, s16 = (lane >> 4) & 1;
    unsigned aA  = sm_u32(A + (m0 + s8 * 8 + l7) * LDA + s16 * 8);
    unsigned aB0 = sm_u32(B + (n0 + s16 * 8 + l7) * LDB + s8 * 8);
    unsigned aB1 = aB0 + 16 * LDB * 2;
#pragma unroll
    for (int ks = 0; ks < KSTEPS; ++ks) {
        unsigned a0, a1, a2, a3, b0, b1, b2, b3;
        ldsm4(aA + ks * 32, a0, a1, a2, a3);
        ldsm4(aB0 + ks * 32, b0, b1, b2, b3);
        mmabf(c[0], a0, a1, a2, a3, b0, b1);
        mmabf(c[1], a0, a1, a2, a3, b2, b3);
        ldsm4(aB1 + ks * 32, b0, b1, b2, b3);
        mmabf(c[2], a0, a1, a2, a3, b0, b1);
        mmabf(c[3], a0, a1, a2, a3, b2, b3);
    }
}

// A-fragment strip cache (K=96, stride 104)
__device__ __forceinline__ void load_afrags(const __nv_bfloat16* __restrict__ A,
                                            int m0, int lane, unsigned af[6][4])
{
    const int l7 = lane & 7, s8 = (lane >> 3) & 1, s16 = (lane >> 4) & 1;
    unsigned aA = sm_u32(A + (m0 + s8 * 8 + l7) * 104 + s16 * 8);
#pragma unroll
    for (int ks = 0; ks < 6; ++ks)
        ldsm4(aA + ks * 32, af[ks][0], af[ks][1], af[ks][2], af[ks][3]);
}

// 16x32 macro-tile with cached A fragments
__device__ __forceinline__ void gemm16x32_ac(const unsigned af[6][4],
                                             const __nv_bfloat16* __restrict__ B,
                                             int n0, int lane, float c[4][4])
{
    const int l7 = lane & 7, s8 = (lane >> 3) & 1, s16 = (lane >> 4) & 1;
    unsigned aB0 = sm_u32(B + (n0 + s16 * 8 + l7) * 104 + s8 * 8);
    unsigned aB1 = aB0 + 16 * 104 * 2;
#pragma unroll
    for (int ks = 0; ks < 6; ++ks) {
        unsigned b0, b1, b2, b3;
        ldsm4(aB0 + ks * 32, b0, b1, b2, b3);
        mmabf(c[0], af[ks][0], af[ks][1], af[ks][2], af[ks][3], b0, b1);
        mmabf(c[1], af[ks][0], af[ks][1], af[ks][2], af[ks][3], b2, b3);
        ldsm4(aB1 + ks * 32, b0, b1, b2, b3);
        mmabf(c[2], af[ks][0], af[ks][1], af[ks][2], af[ks][3], b0, b1);
        mmabf(c[3], af[ks][0], af[ks][1], af[ks][2], af[ks][3], b2, b3);
    }
}

// 32x32 macro-tile (MLP): 4 ldsm per 8 mma
template <int KSTEPS, int LDA, int LDB>
__device__ __forceinline__ void gemm32x32(const __nv_bfloat16* __restrict__ A,
                                          const __nv_bfloat16* __restrict__ B,
                                          int m0, int n0, int lane, float c[2][4][4])
{
    const int l7 = lane & 7, s8 = (lane >> 3) & 1, s16 = (lane >> 4) & 1;
    unsigned aA0 = sm_u32(A + (m0 + s8 * 8 + l7) * LDA + s16 * 8);
    unsigned aA1 = aA0 + 16 * LDA * 2;
    unsigned aB0 = sm_u32(B + (n0 + s16 * 8 + l7) * LDB + s8 * 8);
    unsigned aB1 = aB0 + 16 * LDB * 2;
#pragma unroll
    for (int ks = 0; ks < KSTEPS; ++ks) {
        unsigned a00, a01, a02, a03, a10, a11, a12, a13, b0, b1, b2, b3;
        ldsm4(aA0 + ks * 32, a00, a01, a02, a03);
        ldsm4(aA1 + ks * 32, a10, a11, a12, a13);
        ldsm4(aB0 + ks * 32, b0, b1, b2, b3);
        mmabf(c[0][0], a00, a01, a02, a03, b0, b1);
        mmabf(c[0][1], a00, a01, a02, a03, b2, b3);
        mmabf(c[1][0], a10, a11, a12, a13, b0, b1);
        mmabf(c[1][1], a10, a11, a12, a13, b2, b3);
        ldsm4(aB1 + ks * 32, b0, b1, b2, b3);
        mmabf(c[0][2], a00, a01, a02, a03, b0, b1);
        mmabf(c[0][3], a00, a01, a02, a03, b2, b3);
        mmabf(c[1][2], a10, a11, a12, a13, b0, b1);
        mmabf(c[1][3], a10, a11, a12, a13, b2, b3);
    }
}

__device__ __forceinline__ void st_bf2(__nv_bfloat16* p, float x, float y)
{
    __nv_bfloat162 v = __floats2bfloat162_rn(x, y);
    *reinterpret_cast<__nv_bfloat162*>(p) = v;
}

__device__ __forceinline__ unsigned pack_bf2(float x, float y)
{
    __nv_bfloat162 v = __floats2bfloat162_rn(x, y);
    return *reinterpret_cast<unsigned*>(&v);
}

// stage a 96x96 bf16 weight block into smem stride 104
__device__ __forceinline__ void stage_w(__nv_bfloat16* dst, const __nv_bfloat16* src,
                                        int tid, int nthr)
{
    for (int idx = tid; idx < 96 * 12; idx += nthr) {
        int r = idx / 12, q = idx % 12;
        cpa16(dst + r * 104 + q * 8, src + r * 96 + q * 8);
    }
}

// ---------------- kernel 1 smem layout (bytes) ----------------
#define A_XN 0          // XN; Wproj for the proj phase
#define A_K  23296      // Wv staging, then K
#define A_V  46592      // V
#define A_AO 69888      // Wk staging, then AO
#define A_W  93184      // Wq (resident through flash)
#define SM1_BYTES 113152

// strip K/V gemm: warp w<7 owns 16-row strip w, cached A frags
__device__ __forceinline__ void qkv_strip(const unsigned af[6][4], const __nv_bfloat16* W,
                                          __nv_bfloat16* DST, const float* qkv_b,
                                          int bias_off, int m0, int lane, int g, int t4)
{
#pragma unroll
    for (int nt = 0; nt < 3; ++nt) {
        int n0 = nt * 32;
        float c[4][4] = {};
        gemm16x32_ac(af, W, n0, lane, c);
#pragma unroll
        for (int nn = 0; nn < 4; ++nn) {
            int d = n0 + nn * 8 + 2 * t4;
            float b0 = __ldg(&qkv_b[bias_off + d]);
            float b1 = __ldg(&qkv_b[bias_off + d + 1]);
#pragma unroll
            for (int rh = 0; rh < 2; ++rh) {
                int trow = m0 + g + rh * 8;
                float v0 = c[nn][rh * 2]     + b0;
                float v1 = c[nn][rh * 2 + 1] + b1;
                if (trow >= 98) { v0 = 0.f; v1 = 0.f; }   // K/V pads are reduction dims
                st_bf2(DST + trow * 104 + d, v0, v1);
            }
        }
    }
}

__global__ __launch_bounds__(256, 2)
void attn_kernel(const float* __restrict__ x,
                 const float* __restrict__ n1w, const float* __restrict__ n1b,
                 const float* __restrict__ qkv_b, const float* __restrict__ proj_b)
{
    extern __shared__ char smc[];
    __nv_bfloat16* XN = (__nv_bfloat16*)(smc + A_XN);
    __nv_bfloat16* Kb = (__nv_bfloat16*)(smc + A_K);
    __nv_bfloat16* V  = (__nv_bfloat16*)(smc + A_V);
    __nv_bfloat16* AO = (__nv_bfloat16*)(smc + A_AO);
    __nv_bfloat16* W  = (__nv_bfloat16*)(smc + A_W);
    __shared__ int s_toff[98];

    const int tid = threadIdx.x;
    const int wid = tid >> 5, lane = tid & 31;
    const int g = lane >> 2, t4 = lane & 3;

    // prefetch Wv (into K-buf) and Wq (into W) behind LN
    stage_w(Kb, g_wqkv + 18432, tid, 256);
    stage_w(W, g_wqkv, tid, 256);
    CPA_COMMIT();

    const int widx = blockIdx.x;
    const int b = widx >> 8;
    const int rr = widx & 255;
    const int dblk = rr >> 6, hblk = (rr >> 3) & 7, wblk = rr & 7;
    if (tid < 98) {
        int wd = (tid >= 49);
        int rem = tid - wd * 49;
        int wh = rem / 7, ww = rem - wh * 7;
        s_toff[tid] = (((b * 8 + dblk * 2 + wd) * 56 + hblk * 7 + wh) * 56 + wblk * 7 + ww) * 96;
    }
    // zero XN pad rows
    for (int i = tid; i < 14 * 52; i += 256)
        reinterpret_cast<unsigned*>(XN + 98 * 104)[i] = 0u;
    __syncthreads();   // S1

    // ---- LN1 -> XN bf16 [t][c] ----
    for (int t = wid; t < 98; t += 8) {
        int off = s_toff[t];
        float v0 = x[off + lane];
        float v1 = x[off + lane + 32];
        float v2 = x[off + lane + 64];
        float s = v0 + v1 + v2;
#pragma unroll
        for (int o = 16; o; o >>= 1) s += __shfl_xor_sync(0xffffffffu, s, o);
        float mean = s * (1.f / 96.f);
        float d0 = v0 - mean, d1 = v1 - mean, d2 = v2 - mean;
        float q2 = d0 * d0 + d1 * d1 + d2 * d2;
#pragma unroll
        for (int o = 16; o; o >>= 1) q2 += __shfl_xor_sync(0xffffffffu, q2, o);
        float rstd = rsqrtf(q2 * (1.f / 96.f) + 1e-5f);
        XN[t * 104 + lane] =
            __float2bfloat16_rn(d0 * rstd * __ldg(&n1w[lane]) + __ldg(&n1b[lane]));
        XN[t * 104 + lane + 32] =
            __float2bfloat16_rn(d1 * rstd * __ldg(&n1w[lane + 32]) + __ldg(&n1b[lane + 32]));
        XN[t * 104 + lane + 64] =
            __float2bfloat16_rn(d2 * rstd * __ldg(&n1w[lane + 64]) + __ldg(&n1b[lane + 64]));
    }
    CPA_WAIT0();
    __syncthreads();   // S2: XN + Wv + Wq ready

    stage_w(AO, g_wqkv + 9216, tid, 256);    // Wk (hidden behind V gemm)
    CPA_COMMIT();

    // load XN strip A-fragments once; reused by V gemm, K gemm, AND flash Q gemms
    unsigned axn[6][4];
    if (wid < 7) load_afrags(XN, wid * 16, lane, axn);

    if (wid < 7)
        qkv_strip(axn, Kb, V, qkv_b, 192, wid * 16, lane, g, t4);   // V = XN * Wv
    CPA_WAIT0();
    __syncthreads();   // S3: V + Wk ready; K-buf (Wv) dead

    if (wid < 7)
        qkv_strip(axn, AO, Kb, qkv_b, 96, wid * 16, lane, g, t4);   // K = XN * Wk
    __syncthreads();   // S4: K ready; AO (Wk) dead

    // ---- flash attention: warp w<7 owns m-strip w, loops heads ----
    const int l7 = lane & 7;
    if (wid < 7) {
        const int m0 = wid * 16;
        int i0 = m0 + g;     if (i0 > 97) i0 = 97;
        int i1 = m0 + g + 8; if (i1 > 97) i1 = 97;

        for (int h = 0; h < 3; ++h) {
            const __nv_bfloat16* Kh = Kb + h * 32;

            // Q tile via cached XN A-frags (zero A-side ldsm)
            unsigned qa[2][4];
            {
                float cq[4][4] = {};
                gemm16x32_ac(axn, W, h * 32, lane, cq);
                float qb0[4], qb1[4];
#pragma unroll
                for (int nn = 0; nn < 4; ++nn) {
                    int d = h * 32 + nn * 8 + 2 * t4;
                    qb0[nn] = __ldg(&qkv_b[d]);
                    qb1[nn] = __ldg(&qkv_b[d + 1]);
                }
#pragma unroll
                for (int ks = 0; ks < 2; ++ks) {
                    qa[ks][0] = pack_bf2((cq[2*ks][0] + qb0[2*ks]) * SCALEL,
                                         (cq[2*ks][1] + qb1[2*ks]) * SCALEL);
                    qa[ks][1] = pack_bf2((cq[2*ks][2] + qb0[2*ks]) * SCALEL,
                                         (cq[2*ks][3] + qb1[2*ks]) * SCALEL);
                    qa[ks][2] = pack_bf2((cq[2*ks+1][0] + qb0[2*ks+1]) * SCALEL,
                                         (cq[2*ks+1][1] + qb1[2*ks+1]) * SCALEL);
                    qa[ks][3] = pack_bf2((cq[2*ks+1][2] + qb0[2*ks+1]) * SCALEL,
                                         (cq[2*ks+1][3] + qb1[2*ks+1]) * SCALEL);
                }
            }

            // S tiles -> exp2 immediately -> packed unnormalized probabilities
            const __nv_bfloat16* bi0 = g_bias_bf + h * 10976 + i0 * 112;
            const __nv_bfloat16* bi1 = g_bias_bf + h * 10976 + i1 * 112;
            unsigned pa[7][4];
            float sum0 = 0.f, sum1 = 0.f;
#pragma unroll
            for (int j = 0; j < 7; ++j) {
                float st[2][4];
#pragma unroll
                for (int hf = 0; hf < 2; ++hf)
#pragma unroll
                    for (int e = 0; e < 4; ++e) st[hf][e] = 0.f;
                unsigned aB = sm_u32(Kh + (j * 16 + ((lane >> 4) & 1) * 8 + l7) * 104 +
                                     ((lane >> 3) & 1) * 8);
#pragma unroll
                for (int ks = 0; ks < 2; ++ks) {
                    unsigned b0, b1, b2, b3;
                    ldsm4(aB + ks * 32, b0, b1, b2, b3);
                    mmabf(st[0], qa[ks][0], qa[ks][1], qa[ks][2], qa[ks][3], b0, b1);
                    mmabf(st[1], qa[ks][0], qa[ks][1], qa[ks][2], qa[ks][3], b2, b3);
                }
#pragma unroll
                for (int hf = 0; hf < 2; ++hf) {
                    int col = 16 * j + 8 * hf + 2 * t4;
                    __nv_bfloat162 b0 = *reinterpret_cast<const __nv_bfloat162*>(bi0 + col);
                    __nv_bfloat162 b1 = *reinterpret_cast<const __nv_bfloat162*>(bi1 + col);
                    float e0 = ex2f(st[hf][0] + __bfloat162float(b0.x));
                    float e1 = ex2f(st[hf][1] + __bfloat162float(b0.y));
                    float e2 = ex2f(st[hf][2] + __bfloat162float(b1.x));
                    float e3 = ex2f(st[hf][3] + __bfloat162float(b1.y));
                    sum0 += e0 + e1;
                    sum1 += e2 + e3;
                    pa[j][2 * hf]     = pack_bf2(e0, e1);
                    pa[j][2 * hf + 1] = pack_bf2(e2, e3);
                }
            }
            sum0 += __shfl_xor_sync(0xffffffffu, sum0, 1);
            sum0 += __shfl_xor_sync(0xffffffffu, sum0, 2);
            sum1 += __shfl_xor_sync(0xffffffffu, sum1, 1);
            sum1 += __shfl_xor_sync(0xffffffffu, sum1, 2);
            float r0 = __fdividef(1.f, sum0), r1 = __fdividef(1.f, sum1);

            // PV on unnormalized probabilities
            float o[2][2][4] = {};
#pragma unroll
            for (int j = 0; j < 7; ++j) {
                unsigned vb = sm_u32(V + (j * 16 + ((lane >> 3) & 1) * 8 + l7) * 104 +
                                     h * 32 + ((lane >> 4) & 1) * 8);
                unsigned b0, b1, b2, b3;
                ldsm4t(vb, b0, b1, b2, b3);
                mmabf(o[0][0], pa[j][0], pa[j][1], pa[j][2], pa[j][3], b0, b1);
                mmabf(o[0][1], pa[j][0], pa[j][1], pa[j][2], pa[j][3], b2, b3);
                ldsm4t(vb + 32, b0, b1, b2, b3);
                mmabf(o[1][0], pa[j][0], pa[j][1], pa[j][2], pa[j][3], b0, b1);
                mmabf(o[1][1], pa[j][0], pa[j][1], pa[j][2], pa[j][3], b2, b3);
            }

            // normalize rows and store AO strip
#pragma unroll
            for (int nc = 0; nc < 2; ++nc)
#pragma unroll
                for (int hf = 0; hf < 2; ++hf) {
                    int col = h * 32 + nc * 16 + hf * 8 + 2 * t4;
                    st_bf2(AO + (m0 + g) * 104 + col,
                           o[nc][hf][0] * r0, o[nc][hf][1] * r0);
                    st_bf2(AO + (m0 + g + 8) * 104 + col,
                           o[nc][hf][2] * r1, o[nc][hf][3] * r1);
                }
        }
    }
    __syncthreads();   // S5: flash done; XN dead

    // stage Wproj into XN region
    stage_w(XN, g_wproj, tid, 256);
    CPA_COMMIT();
    CPA_WAIT0();
    __syncthreads();   // S6: Wproj ready

    // ---- proj (strip, cached A) + bias + residual ----
    if (wid < 7) {
        int m0 = wid * 16;
        unsigned aao[6][4];
        load_afrags(AO, m0, lane, aao);
#pragma unroll
        for (int nt = 0; nt < 3; ++nt) {
            int n0 = nt * 32;
            float c[4][4] = {};
            gemm16x32_ac(aao, XN, n0, lane, c);
#pragma unroll
            for (int nn = 0; nn < 4; ++nn) {
                int col = n0 + nn * 8 + 2 * t4;
                float pb0 = __ldg(&proj_b[col]), pb1 = __ldg(&proj_b[col + 1]);
#pragma unroll
                for (int rh = 0; rh < 2; ++rh) {
                    int trow = m0 + g + rh * 8;
                    if (trow < 98) {
                        int off = s_toff[trow] + col;
                        float2 xr = *reinterpret_cast<const float2*>(&x[off]);
                        float2 o2;
                        o2.x = c[nn][rh * 2]     + pb0 + xr.x;
                        o2.y = c[nn][rh * 2 + 1] + pb1 + xr.y;
                        *reinterpret_cast<float2*>(&g_xmid[off]) = o2;
                    }
                }
            }
        }
    }
}

// ---------------- kernel 2 ----------------
#define M_X   0            // bf16 [128][104] = 26624
#define M_H   26624        // bf16 [128][104]
#define M_W1  53248        // bf16 [96][104]  = 19968
#define M_W2A 73216
#define M_W2B 93184
#define SM2_BYTES 113152

__device__ __forceinline__ float gelu_fast(float x)
{
    float u = x * x;
    float w = fmaf(0.03567740814f, u, 0.7978845608f);
    float t = tanhf_hw(x * w);
    return fmaf(x * 0.5f, t, x * 0.5f);
}

__global__ __launch_bounds__(384, 2)
void mlp_kernel(const float* __restrict__ n2w, const float* __restrict__ n2b,
                const float* __restrict__ fc1_b, const float* __restrict__ fc2_b,
                float* __restrict__ out)
{
    extern __shared__ char smc[];
    __nv_bfloat16* X  = (__nv_bfloat16*)(smc + M_X);
    __nv_bfloat16* H  = (__nv_bfloat16*)(smc + M_H);
    __nv_bfloat16* W1 = (__nv_bfloat16*)(smc + M_W1);
    __nv_bfloat16* W2buf[2] = { (__nv_bfloat16*)(smc + M_W2A), (__nv_bfloat16*)(smc + M_W2B) };

    const int tid = threadIdx.x;
    const int wid = tid >> 5, lane = tid & 31;
    const int g = lane >> 2, t4 = lane & 3;
    const int tbase = blockIdx.x * 128;

    const int mt = wid / 3, nt = wid % 3;
    const int m0 = mt * 32, n0 = nt * 32;

    // preload chunk-0 weights (hidden behind LN)
    stage_w(W1, g_fc1, tid, 384);
    for (int idx = tid; idx < 96 * 12; idx += 384) {
        int r = idx / 12, q = idx % 12;
        cpa16(W2buf[0] + r * 104 + q * 8, g_fc2 + r * 384 + q * 8);
    }
    CPA_COMMIT();

    // ---- LN2 -> X bf16 ----
    for (int t = wid; t < 128; t += 12) {
        const float* p = g_xmid + (tbase + t) * 96;
        float v0 = p[lane], v1 = p[lane + 32], v2 = p[lane + 64];
        float s = v0 + v1 + v2;
#pragma unroll
        for (int o = 16; o; o >>= 1) s += __shfl_xor_sync(0xffffffffu, s, o);
        float mean = s * (1.f / 96.f);
        float d0 = v0 - mean, d1 = v1 - mean, d2 = v2 - mean;
        float q2 = d0 * d0 + d1 * d1 + d2 * d2;
#pragma unroll
        for (int o = 16; o; o >>= 1) q2 += __shfl_xor_sync(0xffffffffu, q2, o);
        float rstd = rsqrtf(q2 * (1.f / 96.f) + 1e-5f);
        X[t * 104 + lane] =
            __float2bfloat16_rn(d0 * rstd * __ldg(&n2w[lane]) + __ldg(&n2b[lane]));
        X[t * 104 + lane + 32] =
            __float2bfloat16_rn(d1 * rstd * __ldg(&n2w[lane + 32]) + __ldg(&n2b[lane + 32]));
        X[t * 104 + lane + 64] =
            __float2bfloat16_rn(d2 * rstd * __ldg(&n2w[lane + 64]) + __ldg(&n2b[lane + 64]));
    }

    float c2[2][4][4] = {};   // persistent fc2 accumulators

    for (int ch = 0; ch < 4; ++ch) {
        CPA_WAIT0();
        __syncthreads();

        if (ch < 3) {
            for (int idx = tid; idx < 96 * 12; idx += 384) {
                int r = idx / 12, q = idx % 12;
                cpa16(W2buf[(ch + 1) & 1] + r * 104 + q * 8,
                      g_fc2 + r * 384 + (ch + 1) * 96 + q * 8);
            }
            CPA_COMMIT();
        }

        // fc1 tile + GELU -> H
        {
            float c[2][4][4] = {};
            gemm32x32<6, 104, 104>(X, W1, m0, n0, lane, c);
#pragma unroll
            for (int mf = 0; mf < 2; ++mf)
#pragma unroll
                for (int nn = 0; nn < 4; ++nn) {
                    int col = n0 + nn * 8 + 2 * t4;
                    float b0 = __ldg(&fc1_b[ch * 96 + col]);
                    float b1 = __ldg(&fc1_b[ch * 96 + col + 1]);
#pragma unroll
                    for (int rh = 0; rh < 2; ++rh)
                        st_bf2(H + (m0 + mf * 16 + g + rh * 8) * 104 + col,
                               gelu_fast(c[mf][nn][rh * 2] + b0),
                               gelu_fast(c[mf][nn][rh * 2 + 1] + b1));
                }
        }
        __syncthreads();

        if (ch < 3) {
            stage_w(W1, g_fc1 + (ch + 1) * 96 * 96, tid, 384);
            CPA_COMMIT();
        }

        gemm32x32<6, 104, 104>(H, W2buf[ch & 1], m0, n0, lane, c2);
    }

    // ---- epilogue: bias + residual -> out ----
#pragma unroll
    for (int mf = 0; mf < 2; ++mf)
#pragma unroll
        for (int nn = 0; nn < 4; ++nn) {
            int col = n0 + nn * 8 + 2 * t4;
            float b0 = __ldg(&fc2_b[col]), b1 = __ldg(&fc2_b[col + 1]);
#pragma unroll
            for (int rh = 0; rh < 2; ++rh) {
                int off = (tbase + m0 + mf * 16 + g + rh * 8) * 96 + col;
                float2 xr = *reinterpret_cast<const float2*>(&g_xmid[off]);
                float2 o2;
                o2.x = c2[mf][nn][rh * 2]     + b0 + xr.x;
                o2.y = c2[mf][nn][rh * 2 + 1] + b1 + xr.y;
                *reinterpret_cast<float2*>(&out[off]) = o2;
            }
        }
}

// ---------------- launch ----------------
extern "C" void kernel_launch(void* const* d_in, const int* in_sizes, int n_in,
                              void* d_out, int out_size)
{
    const float* x      = (const float*)d_in[0];
    const float* n1w    = (const float*)d_in[1];
    const float* n1b    = (const float*)d_in[2];
    const float* qkv_w  = (const float*)d_in[3];
    const float* qkv_b  = (const float*)d_in[4];
    const float* proj_w = (const float*)d_in[5];
    const float* proj_b = (const float*)d_in[6];
    const float* rpb    = (const float*)d_in[7];
    const float* n2w    = (const float*)d_in[8];
    const float* n2b    = (const float*)d_in[9];
    const float* fc1_w  = (const float*)d_in[10];
    const float* fc1_b  = (const float*)d_in[11];
    const float* fc2_w  = (const float*)d_in[12];
    const float* fc2_b  = (const float*)d_in[13];
    float* out = (float*)d_out;

    cudaFuncSetAttribute(attn_kernel, cudaFuncAttributeMaxDynamicSharedMemorySize, SM1_BYTES);
    cudaFuncSetAttribute(mlp_kernel,  cudaFuncAttributeMaxDynamicSharedMemorySize, SM2_BYTES);

    prep_kernel<<<128, 256>>>(qkv_w, proj_w, fc1_w, fc2_w, rpb);
    attn_kernel<<<NWIN, 256, SM1_BYTES>>>(x, n1w, n1b, qkv_b, proj_b);
    mlp_kernel<<<NTOKENS / 128, 384, SM2_BYTES>>>(n2w, n2b, fc1_b, fc2_b, out);
}